// round 1
// baseline (speedup 1.0000x reference)
#include <cuda_runtime.h>

// QuantumFeatureExtractor — analytic collapse.
//
// Reference builds a 2^20-dim statevector per batch row, applies RX(x[b,i]+theta[i])
// on each qubit i, then measures <Z_i>. Since every gate acts on a distinct qubit
// starting from |0...0>, the state is a product state and
//   out[b,i] = cos(x[b,i] + theta[i]).
//
// B=16, N=20 -> 320 outputs. One tiny kernel; launch-latency bound.

#define BATCH 16
#define N_QUBITS 20
#define TOTAL (BATCH * N_QUBITS)

__global__ void qfe_kernel(const float* __restrict__ x,
                           const float* __restrict__ theta,
                           float* __restrict__ out) {
    int idx = threadIdx.x;           // 0..319, single block
    if (idx < TOTAL) {
        int q = idx % N_QUBITS;
        // double-precision angle add + cos for headroom vs the reference's
        // fp32 statevector accumulation; cost is irrelevant at this size.
        double ang = (double)x[idx] + (double)theta[q];
        out[idx] = (float)cos(ang);
    }
}

extern "C" void kernel_launch(void* const* d_in, const int* in_sizes, int n_in,
                              void* d_out, int out_size) {
    const float* x     = (const float*)d_in[0];   // [16,20] fp32
    const float* theta = (const float*)d_in[1];   // [20] fp32
    float* out = (float*)d_out;                   // [16,20] fp32
    qfe_kernel<<<1, TOTAL>>>(x, theta, out);
}

// round 2
// speedup vs baseline: 1.2237x; 1.2237x over previous
#include <cuda_runtime.h>

// QuantumFeatureExtractor — analytic collapse, fp32 fast path.
//
// Product-state identity: out[b,i] = cos(x[b,i] + theta[i]).
// 320 outputs total. Round-1 post-mortem: fp64 cos cost ~5us on the weak FP64
// pipe; switch to MUFU-based __cosf (|angle| < ~7, abs err ~1e-6, rel_err
// budget 1e-3). Kernel becomes launch-latency bound.

#define BATCH 16
#define N_QUBITS 20
#define TOTAL (BATCH * N_QUBITS)

__global__ __launch_bounds__(TOTAL, 1)
void qfe_kernel(const float* __restrict__ x,
                const float* __restrict__ theta,
                float* __restrict__ out) {
    int idx = threadIdx.x;           // 0..319, single block
    int q = idx % N_QUBITS;
    float ang = __ldg(&x[idx]) + __ldg(&theta[q]);
    out[idx] = __cosf(ang);          // MUFU.COS fast path
}

extern "C" void kernel_launch(void* const* d_in, const int* in_sizes, int n_in,
                              void* d_out, int out_size) {
    const float* x     = (const float*)d_in[0];   // [16,20] fp32
    const float* theta = (const float*)d_in[1];   // [20] fp32
    float* out = (float*)d_out;                   // [16,20] fp32
    qfe_kernel<<<1, TOTAL>>>(x, theta, out);
}